// round 6
// baseline (speedup 1.0000x reference)
#include <cuda_runtime.h>
#include <math.h>

// GridSelfAttention: N=384, C=128, H=4, D=32
// fp32, packed f32x2 FMA everywhere; this round: occupancy fix
// (512-thread blocks, <=128 regs/thread -> 16 warps/SM instead of 8).

#define NSEQ 384
#define CDIM 128
#define NHEAD 4
#define DHEAD 32
#define NTOK (NSEQ * NSEQ)
#define NNMAT (NSEQ * NSEQ)

typedef unsigned long long u64;
typedef ulonglong2 u64x2;

__device__ __forceinline__ void fma2(u64 &d, u64 a, u64 b) {
    asm("fma.rn.f32x2 %0, %1, %2, %0;" : "+l"(d) : "l"(a), "l"(b));
}
__device__ __forceinline__ float hsum2(u64 v) {
    float x, y;
    asm("mov.b64 {%0,%1}, %2;" : "=f"(x), "=f"(y) : "l"(v));
    return x + y;
}

// ---- scratch (device globals; no allocation allowed) ----
__device__ float g_q[NSEQ * NHEAD * NSEQ * DHEAD];    // [b,h,n,d]
__device__ float g_k[NSEQ * NHEAD * NSEQ * DHEAD];
__device__ float g_v[NSEQ * NHEAD * NSEQ * DHEAD];
__device__ float g_gate[NTOK * CDIM];
__device__ float g_bias[NHEAD * NNMAT];               // [h, i*N+j]
__device__ float g_wa[NTOK * CDIM];

#define MT1 128
#define XPAD 132
#define KPAD 36
#define VTP 388
#define SPD 416

// =====================================================================
// Kernel 1: LN + per-head bias + q/k/v/gate projections
// tile 128x128, 512 threads, 4x8 micro-tiles (<=128 regs -> 16 warps/SM)
// =====================================================================
__global__ __launch_bounds__(512, 1)
void k_proj(const float* __restrict__ pair,
            const float* __restrict__ ln_w,
            const float* __restrict__ ln_b,
            const float* __restrict__ w_bias,
            const float* __restrict__ w_q,
            const float* __restrict__ w_k,
            const float* __restrict__ w_v,
            const float* __restrict__ w_gate)
{
    extern __shared__ float sm[];
    float* Xs = sm;                    // [128][132]
    float* Ws = sm + MT1 * XPAD;       // [128][132]

    const int tid = threadIdx.x;
    const int r0  = blockIdx.x * MT1;

    // load pair tile (4096 float4)
#pragma unroll
    for (int i = 0; i < 8; ++i) {
        int f = tid + i * 512;
        int row = f >> 5, c4 = (f & 31) * 4;
        *(float4*)(Xs + row * XPAD + c4) =
            *(const float4*)(pair + (size_t)(r0 + row) * CDIM + c4);
    }
    __syncthreads();

    // layernorm: 4 threads per row
    {
        int row = tid >> 2, l4 = tid & 3;
        float* xr = Xs + row * XPAD;
        float s = 0.f, s2 = 0.f;
#pragma unroll 8
        for (int c = l4 * 32; c < l4 * 32 + 32; ++c) {
            float x = xr[c]; s += x; s2 += x * x;
        }
        s  += __shfl_xor_sync(0xffffffffu, s, 1);
        s  += __shfl_xor_sync(0xffffffffu, s, 2);
        s2 += __shfl_xor_sync(0xffffffffu, s2, 1);
        s2 += __shfl_xor_sync(0xffffffffu, s2, 2);
        float mean = s * (1.f / 128.f);
        float var  = s2 * (1.f / 128.f) - mean * mean;
        float rstd = rsqrtf(var + 1e-5f);
#pragma unroll 8
        for (int c = l4 * 32; c < l4 * 32 + 32; ++c)
            xr[c] = (xr[c] - mean) * rstd * ln_w[c] + ln_b[c];
    }
    __syncthreads();

    // per-head pair bias: one (row, head) dot per thread (512 = 128x4)
    {
        int row = tid >> 2, h = tid & 3;
        const float* xr = Xs + row * XPAD;
        const float* wb = w_bias + h * CDIM;
        float s = 0.f;
#pragma unroll 8
        for (int c = 0; c < CDIM; ++c) s += xr[c] * wb[c];
        g_bias[(size_t)h * NNMAT + r0 + row] = s;
    }

    // 4 GEMMs: X[128x128] @ W^T[128x128], micro 4x8
    const float* Wp[4] = {w_q, w_k, w_v, w_gate};
    const int tx = tid & 15, ty = tid >> 4;   // ty 0..31

    for (int w = 0; w < 4; ++w) {
        __syncthreads();
        const float* W = Wp[w];
#pragma unroll
        for (int i = 0; i < 8; ++i) {
            int f = tid + i * 512;
            int row = f >> 5, c4 = (f & 31) * 4;
            *(float4*)(Ws + row * XPAD + c4) = *(const float4*)(W + row * CDIM + c4);
        }
        __syncthreads();

        u64 acc[4][8];
#pragma unroll
        for (int i = 0; i < 4; ++i)
#pragma unroll
            for (int j = 0; j < 8; ++j) acc[i][j] = 0ull;

#pragma unroll 2
        for (int kk = 0; kk < CDIM; kk += 4) {
            u64x2 a[4];
#pragma unroll
            for (int i = 0; i < 4; ++i)
                a[i] = *(const u64x2*)(Xs + (i * 32 + ty) * XPAD + kk);
#pragma unroll
            for (int j = 0; j < 8; ++j) {
                u64x2 b = *(const u64x2*)(Ws + (j * 16 + tx) * XPAD + kk);
#pragma unroll
                for (int i = 0; i < 4; ++i) {
                    fma2(acc[i][j], a[i].x, b.x);
                    fma2(acc[i][j], a[i].y, b.y);
                }
            }
        }

        if (w < 3) {
            float* dst = (w == 0) ? g_q : (w == 1) ? g_k : g_v;
#pragma unroll
            for (int i = 0; i < 4; ++i) {
                int r  = r0 + i * 32 + ty;
                int b_ = r / NSEQ;
                int nr = r - b_ * NSEQ;
#pragma unroll
                for (int j = 0; j < 8; ++j) {
                    int n = j * 16 + tx;
                    dst[((size_t)(b_ * NHEAD + (n >> 5)) * NSEQ + nr) * DHEAD + (n & 31)]
                        = hsum2(acc[i][j]);
                }
            }
        } else {
#pragma unroll
            for (int i = 0; i < 4; ++i) {
                int r = r0 + i * 32 + ty;
#pragma unroll
                for (int j = 0; j < 8; ++j) {
                    int n = j * 16 + tx;
                    float v = hsum2(acc[i][j]);
                    g_gate[(size_t)r * CDIM + n] = 1.f / (1.f + __expf(-v));
                }
            }
        }
    }
}

// =====================================================================
// Kernel 2: attention, one (b,h) per block, loops 6 q-tiles of 64.
// 512 threads. QK micro 4x12; softmax 8 lanes/row; PV 8-way split-k 8x4.
// =====================================================================
__global__ __launch_bounds__(512, 1)
void k_attn(const int* __restrict__ mask)
{
    extern __shared__ float sm[];
    float* Ks = sm;                         // 384*36
    float* Vt = Ks + NSEQ * KPAD;           // 32*388
    float* S  = Vt + DHEAD * VTP;           // 64*416
    float* Qs = S  + 64 * SPD;              // 64*36
    float* inv = Qs + 64 * KPAD;            // 64
    int*   Ms = (int*)(inv + 64);           // 384

    const int tid = threadIdx.x;
    const int bh = blockIdx.x;
    const int bb = bh >> 2, h = bh & 3;
    const size_t base = (size_t)bh * NSEQ * DHEAD;
    const float scale = 0.17677669529663687f;   // 1/sqrt(32)

    // fill Ks (3072 float4)
#pragma unroll
    for (int i = 0; i < 6; ++i) {
        int f = tid + i * 512;
        int n = f >> 3, c4 = (f & 7) * 4;
        *(float4*)(Ks + n * KPAD + c4) =
            *(const float4*)(g_k + base + (size_t)n * DHEAD + c4);
    }
    // fill Vt transposed: Vt[d][n], n contiguous
#pragma unroll
    for (int i = 0; i < 6; ++i) {
        int f = tid + i * 512;
        int n = f >> 3, g = f & 7;
        float4 v = *(const float4*)(g_v + base + (size_t)n * DHEAD + g * 4);
        Vt[(g * 4 + 0) * VTP + n] = v.x;
        Vt[(g * 4 + 1) * VTP + n] = v.y;
        Vt[(g * 4 + 2) * VTP + n] = v.z;
        Vt[(g * 4 + 3) * VTP + n] = v.w;
    }
    if (tid < NSEQ) Ms[tid] = mask[bb * NSEQ + tid];
    __syncthreads();

    const float* bias_h = g_bias + (size_t)h * NNMAT;

    for (int qt = 0; qt < 6; ++qt) {
        const int q0 = qt * 64;

        // load Q tile, pre-scaled (512 float4 = 1 pass)
        {
            int n = tid >> 3, c4 = (tid & 7) * 4;
            float4 v = *(const float4*)(g_q + base + (size_t)(q0 + n) * DHEAD + c4);
            v.x *= scale; v.y *= scale; v.z *= scale; v.w *= scale;
            *(float4*)(Qs + n * KPAD + c4) = v;
        }
        __syncthreads();

        // ---- QK^T: micro 4x12 (rows ty*4+i, keys j*32+tx), bias+mask fused ----
        {
            const int tx = tid & 31, ty = tid >> 5;   // ty 0..15
            u64 acc[4][12];
#pragma unroll
            for (int i = 0; i < 4; ++i)
#pragma unroll
                for (int j = 0; j < 12; ++j) acc[i][j] = 0ull;

#pragma unroll
            for (int kk = 0; kk < DHEAD; kk += 4) {
                u64x2 a[4];
#pragma unroll
                for (int i = 0; i < 4; ++i)
                    a[i] = *(const u64x2*)(Qs + (ty * 4 + i) * KPAD + kk);
#pragma unroll
                for (int j = 0; j < 12; ++j) {
                    u64x2 b = *(const u64x2*)(Ks + (j * 32 + tx) * KPAD + kk);
#pragma unroll
                    for (int i = 0; i < 4; ++i) {
                        fma2(acc[i][j], a[i].x, b.x);
                        fma2(acc[i][j], a[i].y, b.y);
                    }
                }
            }
#pragma unroll
            for (int j = 0; j < 12; ++j) {
                int key = j * 32 + tx;
                int km = Ms[key];
                const float* bp = bias_h + (size_t)(q0 + ty * 4) * NSEQ + key;
#pragma unroll
                for (int i = 0; i < 4; ++i) {
                    int m = ty * 4 + i;
                    float l = hsum2(acc[i][j]) + bp[(size_t)i * NSEQ];
                    if (km == 0) l = -1e9f;
                    S[m * SPD + (m & 7) * 4 + key] = l;
                }
            }
        }
        __syncthreads();

        // ---- masked softmax: 8 threads per row (48 keys each) ----
        {
            int row = tid >> 3, l8 = tid & 7;
            float* Sr = S + row * SPD + (row & 7) * 4;
            float mx = -3.0e38f;
#pragma unroll 4
            for (int k2 = l8 * 48; k2 < l8 * 48 + 48; ++k2)
                mx = fmaxf(mx, Sr[k2]);
            mx = fmaxf(mx, __shfl_xor_sync(0xffffffffu, mx, 1));
            mx = fmaxf(mx, __shfl_xor_sync(0xffffffffu, mx, 2));
            mx = fmaxf(mx, __shfl_xor_sync(0xffffffffu, mx, 4));
            float s = 0.f;
#pragma unroll 4
            for (int k2 = l8 * 48; k2 < l8 * 48 + 48; ++k2) {
                float e = __expf(Sr[k2] - mx);
                Sr[k2] = e;
                s += e;
            }
            s += __shfl_xor_sync(0xffffffffu, s, 1);
            s += __shfl_xor_sync(0xffffffffu, s, 2);
            s += __shfl_xor_sync(0xffffffffu, s, 4);
            if (l8 == 0) inv[row] = 1.f / s;
        }
        __syncthreads();

        // ---- P @ V: 8-way split-k (48 keys each), 8x4 micro-tiles ----
        {
            const int kg = tid >> 6, l64 = tid & 63;   // kg 0..7
            const int ry = l64 & 7, cx = l64 >> 3;
            u64 acc[8][4];
#pragma unroll
            for (int i = 0; i < 8; ++i)
#pragma unroll
                for (int j = 0; j < 4; ++j) acc[i][j] = 0ull;

            const int kbase = kg * 48;
#pragma unroll 2
            for (int kk = 0; kk < 48; kk += 4) {
                int k = kbase + kk;
                u64x2 a[8];
#pragma unroll
                for (int i = 0; i < 8; ++i)
                    a[i] = *(const u64x2*)(S + (i * 8 + ry) * SPD + ry * 4 + k);
#pragma unroll
                for (int j = 0; j < 4; ++j) {
                    u64x2 b = *(const u64x2*)(Vt + (j * 8 + cx) * VTP + k);
#pragma unroll
                    for (int i = 0; i < 8; ++i) {
                        fma2(acc[i][j], a[i].x, b.x);
                        fma2(acc[i][j], a[i].y, b.y);
                    }
                }
            }
            __syncthreads();   // all P reads done before scratch overwrite
#pragma unroll
            for (int i = 0; i < 8; ++i)
#pragma unroll
                for (int j = 0; j < 4; ++j)
                    S[kg * 2048 + (i * 8 + ry) * 32 + (j * 8 + cx)] = hsum2(acc[i][j]);
        }
        __syncthreads();

        // ---- reduce 8 partials, normalize, store (float4 per thread) ----
        {
            int o = tid * 4;                       // 512*4 = 2048
            float4 v = *(const float4*)(S + o);
#pragma unroll
            for (int g = 1; g < 8; ++g) {
                float4 p = *(const float4*)(S + g * 2048 + o);
                v.x += p.x; v.y += p.y; v.z += p.z; v.w += p.w;
            }
            int m = o >> 5, d = o & 31;
            float iv = inv[m];
            float* dst = g_wa + (size_t)(bb * NSEQ + q0 + m) * CDIM + h * DHEAD + d;
            dst[0] = v.x * iv; dst[1] = v.y * iv; dst[2] = v.z * iv; dst[3] = v.w * iv;
        }
        __syncthreads();   // before next tile reuses Qs/S
    }
}

// =====================================================================
// Kernel 3: out = (wa * gate) @ w_out^T — tile 128x128, 512 thr, 4x8
// =====================================================================
__global__ __launch_bounds__(512, 1)
void k_out(const float* __restrict__ w_out, float* __restrict__ out)
{
    extern __shared__ float sm[];
    float* Xs = sm;
    float* Ws = sm + MT1 * XPAD;

    const int tid = threadIdx.x;
    const int r0  = blockIdx.x * MT1;

#pragma unroll
    for (int i = 0; i < 8; ++i) {
        int f = tid + i * 512;
        int row = f >> 5, c4 = (f & 31) * 4;
        float4 a = *(const float4*)(g_wa + (size_t)(r0 + row) * CDIM + c4);
        float4 g = *(const float4*)(g_gate + (size_t)(r0 + row) * CDIM + c4);
        a.x *= g.x; a.y *= g.y; a.z *= g.z; a.w *= g.w;
        *(float4*)(Xs + row * XPAD + c4) = a;
    }
#pragma unroll
    for (int i = 0; i < 8; ++i) {
        int f = tid + i * 512;
        int row = f >> 5, c4 = (f & 31) * 4;
        *(float4*)(Ws + row * XPAD + c4) = *(const float4*)(w_out + row * CDIM + c4);
    }
    __syncthreads();

    const int tx = tid & 15, ty = tid >> 4;   // ty 0..31
    u64 acc[4][8];
#pragma unroll
    for (int i = 0; i < 4; ++i)
#pragma unroll
        for (int j = 0; j < 8; ++j) acc[i][j] = 0ull;

#pragma unroll 2
    for (int kk = 0; kk < CDIM; kk += 4) {
        u64x2 a[4];
#pragma unroll
        for (int i = 0; i < 4; ++i)
            a[i] = *(const u64x2*)(Xs + (i * 32 + ty) * XPAD + kk);
#pragma unroll
        for (int j = 0; j < 8; ++j) {
            u64x2 b = *(const u64x2*)(Ws + (j * 16 + tx) * XPAD + kk);
#pragma unroll
            for (int i = 0; i < 4; ++i) {
                fma2(acc[i][j], a[i].x, b.x);
                fma2(acc[i][j], a[i].y, b.y);
            }
        }
    }

#pragma unroll
    for (int i = 0; i < 4; ++i) {
        int r = r0 + i * 32 + ty;
#pragma unroll
        for (int j = 0; j < 8; ++j) {
            int n = j * 16 + tx;
            out[(size_t)r * CDIM + n] = hsum2(acc[i][j]);
        }
    }
}

// =====================================================================
extern "C" void kernel_launch(void* const* d_in, const int* in_sizes, int n_in,
                              void* d_out, int out_size)
{
    const float* pair   = (const float*)d_in[0];
    const int*   mask   = (const int*)  d_in[1];
    const float* ln_w   = (const float*)d_in[2];
    const float* ln_b   = (const float*)d_in[3];
    const float* w_bias = (const float*)d_in[4];
    const float* w_q    = (const float*)d_in[5];
    const float* w_k    = (const float*)d_in[6];
    const float* w_v    = (const float*)d_in[7];
    const float* w_gate = (const float*)d_in[8];
    const float* w_out  = (const float*)d_in[9];
    float* out = (float*)d_out;

    const int smem1 = 2 * MT1 * XPAD * (int)sizeof(float);                    // 135168 B
    const int smem2 = (NSEQ * KPAD + DHEAD * VTP + 64 * SPD + 64 * KPAD + 64)
                        * (int)sizeof(float) + NSEQ * (int)sizeof(int);       // 222464 B

    cudaFuncSetAttribute(k_proj, cudaFuncAttributeMaxDynamicSharedMemorySize, smem1);
    cudaFuncSetAttribute(k_attn, cudaFuncAttributeMaxDynamicSharedMemorySize, smem2);
    cudaFuncSetAttribute(k_out,  cudaFuncAttributeMaxDynamicSharedMemorySize, smem1);

    k_proj<<<NTOK / MT1, 512, smem1>>>(pair, ln_w, ln_b, w_bias, w_q, w_k, w_v, w_gate);
    k_attn<<<NSEQ * NHEAD, 512, smem2>>>(mask);
    k_out<<<NTOK / MT1, 512, smem1>>>(w_out, out);
}